// round 6
// baseline (speedup 1.0000x reference)
#include <cuda_runtime.h>
#include <cuda_fp16.h>
#include <math.h>

// ---------------- problem-size constants ----------------
#define MAXN 100000
#define MAXE 1200000
#define F_IN  64
#define F_HID 64
#define F_OUT 16
#define SCAN_B 256

// ---------------- device scratch (zero at load; re-zeroed at end of agg2) ----
__device__ __half g_y_h[MAXN * F_HID];   // x @ W1, fp16
__device__ __half g_h_h[MAXN * F_HID];   // relu layer-1 output, fp16
__device__ __half g_z_h[MAXN * F_OUT];   // h @ W2, fp16
__device__ int    g_deg[MAXN];           // out-degree by row (for dinv)
__device__ int    g_cnt[MAXN];           // in-degree by col; alloc rewrites as cnt+1
__device__ float  g_dinv[MAXN];
__device__ int    g_start[MAXN];         // CSR row_ptr (incl. self edge)
__device__ int    g_cursor[MAXN];        // fill cursors
__device__ int    g_total;               // global CSR allocation cursor
__device__ int2   g_edge[MAXE + MAXN];   // packed (src, coef bits); self edge first

// ---------------- kernels ----------------

// Histogram both endpoints. Assumes g_deg/g_cnt are zero on entry.
__global__ void hist_kernel(const int* __restrict__ ei, int E) {
    int e = blockIdx.x * blockDim.x + threadIdx.x;
    if (e < E) {
        atomicAdd(&g_deg[ei[e]], 1);
        atomicAdd(&g_cnt[ei[E + e]], 1);
    }
}

// CSR allocation: block scan of (cnt+1), global atomic base, dinv, and the
// self edge written at start[i]. Cursor begins after the self edge.
__global__ __launch_bounds__(SCAN_B) void alloc_kernel(int N) {
    __shared__ int s[SCAN_B];
    __shared__ int base_sm;
    int t = threadIdx.x;
    int i = blockIdx.x * SCAN_B + t;
    int v = (i < N) ? (g_cnt[i] + 1) : 0;      // +1 for self loop
    s[t] = v;
    float di = 0.f;
    if (i < N) {
        di = rsqrtf((float)(g_deg[i] + 1));
        g_dinv[i] = di;
    }
    __syncthreads();
    for (int off = 1; off < SCAN_B; off <<= 1) {
        int u = (t >= off) ? s[t - off] : 0;
        __syncthreads();
        s[t] += u;
        __syncthreads();
    }
    if (t == SCAN_B - 1) base_sm = atomicAdd(&g_total, s[t]);
    __syncthreads();
    if (i < N) {
        int st = base_sm + s[t] - v;
        g_start[i] = st;
        g_cursor[i] = st + 1;
        g_cnt[i] = v;                          // count including self
        g_edge[st] = make_int2(i, __float_as_int(di * di));  // self edge
    }
}

// Fill CSR with the real edges.
__global__ void fill_kernel(const int* __restrict__ ei, int E) {
    int e = blockIdx.x * blockDim.x + threadIdx.x;
    if (e < E) {
        int r = ei[e];
        int c = ei[E + e];
        float coef = g_dinv[r] * g_dinv[c];
        int pos = atomicAdd(&g_cursor[c], 1);
        g_edge[pos] = make_int2(r, __float_as_int(coef));
    }
}

// y = x @ W1   ([N,64] @ [64,64]) -> fp16
__global__ __launch_bounds__(256) void gemm1_kernel(const float* __restrict__ x,
                                                    const float* __restrict__ W,
                                                    int N) {
    __shared__ float Ws[64 * 64];
    __shared__ float xs[16 * 64];
    int tx = threadIdx.x;
    int ty = threadIdx.y;
    int tid = ty * 64 + tx;

    for (int i = tid; i < 64 * 64; i += 256) Ws[i] = W[i];

    int row0 = blockIdx.x * 16;
    {
        int r  = tid >> 4;
        int cc = tid & 15;
        int gr = row0 + r;
        float4 v = (gr < N) ? reinterpret_cast<const float4*>(x)[(size_t)gr * 16 + cc]
                            : make_float4(0.f, 0.f, 0.f, 0.f);
        reinterpret_cast<float4*>(xs)[r * 16 + cc] = v;
    }
    __syncthreads();

    float acc[4] = {0.f, 0.f, 0.f, 0.f};
#pragma unroll
    for (int k = 0; k < 64; k++) {
        float w = Ws[k * 64 + tx];
#pragma unroll
        for (int r = 0; r < 4; r++) acc[r] += xs[(ty * 4 + r) * 64 + k] * w;
    }
#pragma unroll
    for (int r = 0; r < 4; r++) {
        float other = __shfl_xor_sync(0xffffffffu, acc[r], 1);
        int gr = row0 + ty * 4 + r;
        if ((tx & 1) == 0 && gr < N) {
            __half2 hv = __floats2half2_rn(acc[r], other);
            reinterpret_cast<__half2*>(g_y_h)[(size_t)gr * 32 + (tx >> 1)] = hv;
        }
    }
}

// Layer-1 aggregation: pure CSR gather (self edge included) + bias + relu -> h fp16.
// One warp per node; 4 neighbor rows in flight.
__global__ __launch_bounds__(256) void agg1_kernel(const float* __restrict__ b1, int N) {
    int tid = threadIdx.x;
    int warp = (blockIdx.x * blockDim.x + tid) >> 5;
    if (warp >= N) return;
    int lane = tid & 31;
    int slot = lane >> 3;     // 0..3
    int q = lane & 7;         // uint4 (8-half) chunk within the 128B row

    int start = g_start[warp];
    int cnt = g_cnt[warp];

    float a[8];
#pragma unroll
    for (int i = 0; i < 8; i++) a[i] = 0.f;

    const uint4* yrows = reinterpret_cast<const uint4*>(g_y_h);
    for (int j = slot; j < cnt; j += 4) {
        int2 rec = g_edge[start + j];
        float c = __int_as_float(rec.y);
        uint4 v = yrows[(size_t)rec.x * 8 + q];
        float2 f;
        f = __half22float2(*reinterpret_cast<__half2*>(&v.x)); a[0] += c * f.x; a[1] += c * f.y;
        f = __half22float2(*reinterpret_cast<__half2*>(&v.y)); a[2] += c * f.x; a[3] += c * f.y;
        f = __half22float2(*reinterpret_cast<__half2*>(&v.z)); a[4] += c * f.x; a[5] += c * f.y;
        f = __half22float2(*reinterpret_cast<__half2*>(&v.w)); a[6] += c * f.x; a[7] += c * f.y;
    }
#pragma unroll
    for (int i = 0; i < 8; i++) {
        a[i] += __shfl_xor_sync(0xffffffffu, a[i], 8);
        a[i] += __shfl_xor_sync(0xffffffffu, a[i], 16);
    }

    if (lane < 8) {
        float4 bb0 = reinterpret_cast<const float4*>(b1)[q * 2];
        float4 bb1 = reinterpret_cast<const float4*>(b1)[q * 2 + 1];
        __half2 p0 = __floats2half2_rn(fmaxf(a[0] + bb0.x, 0.f), fmaxf(a[1] + bb0.y, 0.f));
        __half2 p1 = __floats2half2_rn(fmaxf(a[2] + bb0.z, 0.f), fmaxf(a[3] + bb0.w, 0.f));
        __half2 p2 = __floats2half2_rn(fmaxf(a[4] + bb1.x, 0.f), fmaxf(a[5] + bb1.y, 0.f));
        __half2 p3 = __floats2half2_rn(fmaxf(a[6] + bb1.z, 0.f), fmaxf(a[7] + bb1.w, 0.f));
        uint4 o;
        o.x = *reinterpret_cast<unsigned*>(&p0);
        o.y = *reinterpret_cast<unsigned*>(&p1);
        o.z = *reinterpret_cast<unsigned*>(&p2);
        o.w = *reinterpret_cast<unsigned*>(&p3);
        reinterpret_cast<uint4*>(g_h_h)[(size_t)warp * 8 + q] = o;
    }
}

// z = h @ W2  ([N,64] fp16 @ [64,16]) -> fp16. 64 rows per 256-thread block.
__global__ __launch_bounds__(256) void gemm2_kernel(const float* __restrict__ W2, int N) {
    __shared__ __half h_sm[64 * 72];   // padded rows (144B) to dodge bank conflicts
    __shared__ float  W2t[16 * 64];    // transposed: W2t[c][k]
    int tid = threadIdx.x;

    for (int i = tid; i < 1024; i += 256) {
        int k = i >> 4, c = i & 15;
        W2t[c * 64 + k] = W2[i];
    }
    int row0 = blockIdx.x * 64;
    for (int m = tid; m < 512; m += 256) {
        int r = m >> 3, c16 = m & 7;
        int gr = row0 + r;
        uint4 v = (gr < N) ? reinterpret_cast<const uint4*>(g_h_h)[(size_t)gr * 8 + c16]
                           : make_uint4(0u, 0u, 0u, 0u);
        *reinterpret_cast<uint4*>(&h_sm[r * 72 + c16 * 8]) = v;
    }
    __syncthreads();

    int r = tid >> 2;        // 0..63
    int u = tid & 3;         // col group: cols 4u..4u+3
    int gr = row0 + r;
    float acc[4] = {0.f, 0.f, 0.f, 0.f};
#pragma unroll
    for (int kq = 0; kq < 16; kq++) {
        uint2 hv = *reinterpret_cast<const uint2*>(&h_sm[r * 72 + kq * 4]);
        float2 f0 = __half22float2(*reinterpret_cast<__half2*>(&hv.x));
        float2 f1 = __half22float2(*reinterpret_cast<__half2*>(&hv.y));
#pragma unroll
        for (int j = 0; j < 4; j++) {
            float4 w = *reinterpret_cast<const float4*>(&W2t[(4 * u + j) * 64 + kq * 4]);
            acc[j] += f0.x * w.x + f0.y * w.y + f1.x * w.z + f1.y * w.w;
        }
    }
    if (gr < N) {
        __half2 p0 = __floats2half2_rn(acc[0], acc[1]);
        __half2 p1 = __floats2half2_rn(acc[2], acc[3]);
        uint2 o;
        o.x = *reinterpret_cast<unsigned*>(&p0);
        o.y = *reinterpret_cast<unsigned*>(&p1);
        reinterpret_cast<uint2*>(g_z_h)[(size_t)gr * 4 + u] = o;
    }
}

// Layer-2 aggregation + bias + log_softmax -> out. Self edge is in the CSR.
// Also re-zeroes g_deg/g_cnt/g_total for the next graph replay.
__global__ __launch_bounds__(256) void agg2_kernel(const float* __restrict__ b2,
                                                   float* __restrict__ out, int N) {
    int tid = threadIdx.x;
    int warp = (blockIdx.x * blockDim.x + tid) >> 5;
    if (warp >= N) return;
    int lane = tid & 31;

    int start = g_start[warp];
    int cnt = g_cnt[warp];
    __syncwarp();
    if (lane == 0) { g_deg[warp] = 0; g_cnt[warp] = 0; }
    if (warp == 0 && lane == 1) g_total = 0;

    int slot = lane >> 2;    // 0..7
    int q = lane & 3;        // uint2 (4-half) chunk within the 32B row

    float a[4];
#pragma unroll
    for (int i = 0; i < 4; i++) a[i] = 0.f;

    const uint2* zrows = reinterpret_cast<const uint2*>(g_z_h);
    for (int j = slot; j < cnt; j += 8) {
        int2 rec = g_edge[start + j];
        float coef = __int_as_float(rec.y);
        uint2 v = zrows[(size_t)rec.x * 4 + q];
        float2 f0 = __half22float2(*reinterpret_cast<__half2*>(&v.x));
        float2 f1 = __half22float2(*reinterpret_cast<__half2*>(&v.y));
        a[0] += coef * f0.x;  a[1] += coef * f0.y;
        a[2] += coef * f1.x;  a[3] += coef * f1.y;
    }
#pragma unroll
    for (int i = 0; i < 4; i++) {
        a[i] += __shfl_xor_sync(0xffffffffu, a[i], 4);
        a[i] += __shfl_xor_sync(0xffffffffu, a[i], 8);
        a[i] += __shfl_xor_sync(0xffffffffu, a[i], 16);
    }

    float4 bb = reinterpret_cast<const float4*>(b2)[q];
    float4 l;
    l.x = a[0] + bb.x;
    l.y = a[1] + bb.y;
    l.z = a[2] + bb.z;
    l.w = a[3] + bb.w;

    float m4 = fmaxf(fmaxf(l.x, l.y), fmaxf(l.z, l.w));
    m4 = fmaxf(m4, __shfl_xor_sync(0xffffffffu, m4, 1));
    m4 = fmaxf(m4, __shfl_xor_sync(0xffffffffu, m4, 2));
    float se = __expf(l.x - m4) + __expf(l.y - m4) + __expf(l.z - m4) + __expf(l.w - m4);
    se += __shfl_xor_sync(0xffffffffu, se, 1);
    se += __shfl_xor_sync(0xffffffffu, se, 2);
    float lse = m4 + __logf(se);

    if (lane < 4) {
        float4 o;
        o.x = l.x - lse;
        o.y = l.y - lse;
        o.z = l.z - lse;
        o.w = l.w - lse;
        reinterpret_cast<float4*>(out)[(size_t)warp * 4 + q] = o;
    }
}

// ---------------- launch ----------------
extern "C" void kernel_launch(void* const* d_in, const int* in_sizes, int n_in,
                              void* d_out, int out_size) {
    const float* x  = (const float*)d_in[0];
    const int*   ei = (const int*)d_in[1];   // int32 (JAX x64 disabled)
    const float* W1 = (const float*)d_in[2];
    const float* b1 = (const float*)d_in[3];
    const float* W2 = (const float*)d_in[4];
    const float* b2 = (const float*)d_in[5];
    float*       out = (float*)d_out;

    int N = in_sizes[0] / F_IN;
    int E = in_sizes[1] / 2;
    const int TB = 256;

    hist_kernel<<<(E + TB - 1) / TB, TB>>>(ei, E);
    alloc_kernel<<<(N + SCAN_B - 1) / SCAN_B, SCAN_B>>>(N);
    fill_kernel<<<(E + TB - 1) / TB, TB>>>(ei, E);

    gemm1_kernel<<<(N + 15) / 16, dim3(64, 4)>>>(x, W1, N);

    long long a1_threads = (long long)N * 32;
    agg1_kernel<<<(unsigned)((a1_threads + TB - 1) / TB), TB>>>(b1, N);

    gemm2_kernel<<<(N + 63) / 64, TB>>>(W2, N);

    long long a2_threads = (long long)N * 32;
    agg2_kernel<<<(unsigned)((a2_threads + TB - 1) / TB), TB>>>(b2, out, N);
}

// round 7
// speedup vs baseline: 1.2432x; 1.2432x over previous
#include <cuda_runtime.h>
#include <cuda_fp16.h>
#include <math.h>

// ---------------- problem-size constants ----------------
#define MAXN 100000
#define MAXE 1200000
#define F_IN  64
#define F_HID 64
#define F_OUT 16
#define SCAN_B 256

// ---------------- device scratch (zero at load; re-zeroed at end of agg2) ----
__device__ __half g_y_h[MAXN * F_HID];   // x @ W1, fp16
__device__ __half g_z_h[MAXN * F_OUT];   // h @ W2, fp16
__device__ int    g_deg[MAXN];           // out-degree by row (for dinv)
__device__ int    g_cnt[MAXN];           // in-degree by col (CSR counts)
__device__ float  g_dinv[MAXN];
__device__ int    g_start[MAXN];         // CSR row_ptr
__device__ int    g_cursor[MAXN];        // fill cursors
__device__ int    g_total;               // global CSR allocation cursor
__device__ int2   g_edge[MAXE];          // packed (src, coef bits), bucketed by col

// ---------------- kernels ----------------

// Histogram both endpoints. Assumes g_deg/g_cnt are zero on entry
// (true at module load; agg2 re-zeroes them every invocation).
__global__ void hist_kernel(const int* __restrict__ ei, int E) {
    int e = blockIdx.x * blockDim.x + threadIdx.x;
    if (e < E) {
        atomicAdd(&g_deg[ei[e]], 1);
        atomicAdd(&g_cnt[ei[E + e]], 1);
    }
}

// CSR allocation in ONE kernel: block-local inclusive scan of cnt + a single
// global atomicAdd per block for the base. Also computes dinv.
__global__ __launch_bounds__(SCAN_B) void alloc_kernel(int N) {
    __shared__ int s[SCAN_B];
    __shared__ int base_sm;
    int t = threadIdx.x;
    int i = blockIdx.x * SCAN_B + t;
    int v = (i < N) ? g_cnt[i] : 0;
    s[t] = v;
    if (i < N) g_dinv[i] = rsqrtf((float)(g_deg[i] + 1));
    __syncthreads();
    for (int off = 1; off < SCAN_B; off <<= 1) {
        int u = (t >= off) ? s[t - off] : 0;
        __syncthreads();
        s[t] += u;
        __syncthreads();
    }
    if (t == SCAN_B - 1) base_sm = atomicAdd(&g_total, s[t]);
    __syncthreads();
    if (i < N) {
        int st = base_sm + s[t] - v;
        g_start[i] = st;
        g_cursor[i] = st;
    }
}

// Fill CSR: packed (src, coef) records bucketed by col.
__global__ void fill_kernel(const int* __restrict__ ei, int E) {
    int e = blockIdx.x * blockDim.x + threadIdx.x;
    if (e < E) {
        int r = ei[e];
        int c = ei[E + e];
        float coef = g_dinv[r] * g_dinv[c];
        int pos = atomicAdd(&g_cursor[c], 1);
        g_edge[pos] = make_int2(r, __float_as_int(coef));
    }
}

// y = x @ W1 ([N,64] @ [64,64]) via HMMA m16n8k16, fp16 in / f32 accum / fp16 out.
// 256 threads = 8 warps; block covers 128 rows; each warp 16 rows x 64 cols.
__global__ __launch_bounds__(256) void gemm1_kernel(const float* __restrict__ x,
                                                    const float* __restrict__ W,
                                                    int N) {
    __shared__ __half xs[128 * 72];    // x tile fp16, row stride 72 (bank-safe)
    __shared__ __half W1t[64 * 72];    // W1 transposed: W1t[n][k]
    int tid  = threadIdx.x;
    int lane = tid & 31;
    int warp = tid >> 5;

    // W1 f32 row-major [k][n] -> fp16 transposed [n][k]
    for (int i = tid; i < 4096; i += 256) {
        int k = i >> 6, n = i & 63;
        W1t[n * 72 + k] = __float2half(W[i]);
    }

    int row0 = blockIdx.x * 128;
    // x tile: 128 rows x 16 float4, convert to fp16
    for (int i = tid; i < 2048; i += 256) {
        int r = i >> 4, c4 = i & 15;
        int gr = row0 + r;
        float4 v = (gr < N) ? reinterpret_cast<const float4*>(x)[(size_t)gr * 16 + c4]
                            : make_float4(0.f, 0.f, 0.f, 0.f);
        __half2 p0 = __floats2half2_rn(v.x, v.y);
        __half2 p1 = __floats2half2_rn(v.z, v.w);
        *reinterpret_cast<__half2*>(&xs[r * 72 + c4 * 4])     = p0;
        *reinterpret_cast<__half2*>(&xs[r * 72 + c4 * 4 + 2]) = p1;
    }
    __syncthreads();

    int rbase = warp * 16;
    int r  = lane >> 2;        // 0..7 (fragment row group)
    int kq = (lane & 3) * 2;   // fragment k offset

    float acc[8][4];
#pragma unroll
    for (int nt = 0; nt < 8; nt++)
#pragma unroll
        for (int j = 0; j < 4; j++) acc[nt][j] = 0.f;

#pragma unroll
    for (int kc = 0; kc < 4; kc++) {
        int k0 = kc * 16;
        unsigned a0 = *reinterpret_cast<unsigned*>(&xs[(rbase + r)     * 72 + k0 + kq]);
        unsigned a1 = *reinterpret_cast<unsigned*>(&xs[(rbase + r + 8) * 72 + k0 + kq]);
        unsigned a2 = *reinterpret_cast<unsigned*>(&xs[(rbase + r)     * 72 + k0 + kq + 8]);
        unsigned a3 = *reinterpret_cast<unsigned*>(&xs[(rbase + r + 8) * 72 + k0 + kq + 8]);
#pragma unroll
        for (int nt = 0; nt < 8; nt++) {
            int n = nt * 8 + r;
            unsigned b0 = *reinterpret_cast<unsigned*>(&W1t[n * 72 + k0 + kq]);
            unsigned b1 = *reinterpret_cast<unsigned*>(&W1t[n * 72 + k0 + kq + 8]);
            asm volatile(
                "mma.sync.aligned.m16n8k16.row.col.f32.f16.f16.f32 "
                "{%0,%1,%2,%3}, {%4,%5,%6,%7}, {%8,%9}, {%0,%1,%2,%3};"
                : "+f"(acc[nt][0]), "+f"(acc[nt][1]), "+f"(acc[nt][2]), "+f"(acc[nt][3])
                : "r"(a0), "r"(a1), "r"(a2), "r"(a3), "r"(b0), "r"(b1));
        }
    }

    // write C: c0,c1 -> row r, cols (lane&3)*2 + nt*8; c2,c3 -> row r+8
    int gr0 = row0 + rbase + r;
    int gr1 = gr0 + 8;
#pragma unroll
    for (int nt = 0; nt < 8; nt++) {
        int col = nt * 8 + (lane & 3) * 2;
        __half2 p0 = __floats2half2_rn(acc[nt][0], acc[nt][1]);
        __half2 p1 = __floats2half2_rn(acc[nt][2], acc[nt][3]);
        if (gr0 < N) *reinterpret_cast<__half2*>(&g_y_h[(size_t)gr0 * 64 + col]) = p0;
        if (gr1 < N) *reinterpret_cast<__half2*>(&g_y_h[(size_t)gr1 * 64 + col]) = p1;
    }
}

// Fused: aggr1 (CSR gather of fp16 rows) + self loop + bias + relu -> h (smem)
//        -> z = h @ W2 -> fp16. One warp per node; 4 neighbors in flight.
__global__ __launch_bounds__(256) void agg1_kernel(const float* __restrict__ b1,
                                                   const float* __restrict__ W2,
                                                   int N) {
    __shared__ float W2s[64 * 16];
    __shared__ float h_sm[8][64];
    int tid = threadIdx.x;
    for (int i = tid; i < 64 * 16; i += 256) W2s[i] = W2[i];
    __syncthreads();

    int warp = (blockIdx.x * blockDim.x + tid) >> 5;
    if (warp >= N) return;
    int lane = tid & 31;
    int w = tid >> 5;

    int start = g_start[warp];
    int cnt = g_cnt[warp];
    int slot = lane >> 3;     // 0..3 neighbor slot
    int q = lane & 7;         // uint4 (8-half) chunk within 128B row

    float a[8];
#pragma unroll
    for (int i = 0; i < 8; i++) a[i] = 0.f;

    const uint4* yrows = reinterpret_cast<const uint4*>(g_y_h);
    for (int j = slot; j < cnt; j += 4) {
        int2 rec = g_edge[start + j];
        float coef = __int_as_float(rec.y);
        uint4 v = yrows[(size_t)rec.x * 8 + q];
        float2 f;
        f = __half22float2(*reinterpret_cast<__half2*>(&v.x)); a[0] += coef * f.x; a[1] += coef * f.y;
        f = __half22float2(*reinterpret_cast<__half2*>(&v.y)); a[2] += coef * f.x; a[3] += coef * f.y;
        f = __half22float2(*reinterpret_cast<__half2*>(&v.z)); a[4] += coef * f.x; a[5] += coef * f.y;
        f = __half22float2(*reinterpret_cast<__half2*>(&v.w)); a[6] += coef * f.x; a[7] += coef * f.y;
    }
#pragma unroll
    for (int i = 0; i < 8; i++) {
        a[i] += __shfl_xor_sync(0xffffffffu, a[i], 8);
        a[i] += __shfl_xor_sync(0xffffffffu, a[i], 16);
    }

    if (lane < 8) {
        float di = g_dinv[warp];
        float s = di * di;
        uint4 yv = yrows[(size_t)warp * 8 + q];
        float2 y0 = __half22float2(*reinterpret_cast<__half2*>(&yv.x));
        float2 y1 = __half22float2(*reinterpret_cast<__half2*>(&yv.y));
        float2 y2 = __half22float2(*reinterpret_cast<__half2*>(&yv.z));
        float2 y3 = __half22float2(*reinterpret_cast<__half2*>(&yv.w));
        float4 bb0 = reinterpret_cast<const float4*>(b1)[q * 2];
        float4 bb1 = reinterpret_cast<const float4*>(b1)[q * 2 + 1];
        float4 h0, h1;
        h0.x = fmaxf(a[0] + s * y0.x + bb0.x, 0.f);
        h0.y = fmaxf(a[1] + s * y0.y + bb0.y, 0.f);
        h0.z = fmaxf(a[2] + s * y1.x + bb0.z, 0.f);
        h0.w = fmaxf(a[3] + s * y1.y + bb0.w, 0.f);
        h1.x = fmaxf(a[4] + s * y2.x + bb1.x, 0.f);
        h1.y = fmaxf(a[5] + s * y2.y + bb1.y, 0.f);
        h1.z = fmaxf(a[6] + s * y3.x + bb1.z, 0.f);
        h1.w = fmaxf(a[7] + s * y3.y + bb1.w, 0.f);
        reinterpret_cast<float4*>(h_sm[w])[q * 2]     = h0;
        reinterpret_cast<float4*>(h_sm[w])[q * 2 + 1] = h1;
    }
    __syncwarp();

    // z[warp] = h @ W2  (64 -> 16), lanes 0..15 each compute one output
    float accz = 0.f;
    if (lane < 16) {
#pragma unroll
        for (int k = 0; k < 64; k++) accz += h_sm[w][k] * W2s[k * 16 + lane];
    }
    float otherz = __shfl_xor_sync(0xffffffffu, accz, 1);
    if (lane < 16 && (lane & 1) == 0) {
        __half2 hz = __floats2half2_rn(accz, otherz);
        reinterpret_cast<__half2*>(g_z_h)[(size_t)warp * 8 + (lane >> 1)] = hz;
    }
}

// Fused: aggr2 (CSR gather of fp16 rows) + self loop + bias + log_softmax -> out.
// Also re-zeroes g_deg/g_cnt/g_total for the next graph replay.
__global__ __launch_bounds__(256) void agg2_kernel(const float* __restrict__ b2,
                                                   float* __restrict__ out, int N) {
    int tid = threadIdx.x;
    int warp = (blockIdx.x * blockDim.x + tid) >> 5;
    if (warp >= N) return;
    int lane = tid & 31;

    int start = g_start[warp];
    int cnt = g_cnt[warp];
    __syncwarp();
    if (lane == 0) { g_deg[warp] = 0; g_cnt[warp] = 0; }
    if (warp == 0 && lane == 1) g_total = 0;

    int slot = lane >> 2;    // 0..7 neighbor slot
    int q = lane & 3;        // uint2 (4-half) chunk within 32B row

    float a[4];
#pragma unroll
    for (int i = 0; i < 4; i++) a[i] = 0.f;

    const uint2* zrows = reinterpret_cast<const uint2*>(g_z_h);
    for (int j = slot; j < cnt; j += 8) {
        int2 rec = g_edge[start + j];
        float coef = __int_as_float(rec.y);
        uint2 v = zrows[(size_t)rec.x * 4 + q];
        float2 f0 = __half22float2(*reinterpret_cast<__half2*>(&v.x));
        float2 f1 = __half22float2(*reinterpret_cast<__half2*>(&v.y));
        a[0] += coef * f0.x;  a[1] += coef * f0.y;
        a[2] += coef * f1.x;  a[3] += coef * f1.y;
    }
#pragma unroll
    for (int i = 0; i < 4; i++) {
        a[i] += __shfl_xor_sync(0xffffffffu, a[i], 4);
        a[i] += __shfl_xor_sync(0xffffffffu, a[i], 8);
        a[i] += __shfl_xor_sync(0xffffffffu, a[i], 16);
    }

    float di = g_dinv[warp];
    float s = di * di;
    uint2 zv = zrows[(size_t)warp * 4 + q];
    float2 z0 = __half22float2(*reinterpret_cast<__half2*>(&zv.x));
    float2 z1 = __half22float2(*reinterpret_cast<__half2*>(&zv.y));
    float4 bb = reinterpret_cast<const float4*>(b2)[q];
    float4 l;
    l.x = a[0] + s * z0.x + bb.x;
    l.y = a[1] + s * z0.y + bb.y;
    l.z = a[2] + s * z1.x + bb.z;
    l.w = a[3] + s * z1.y + bb.w;

    float m4 = fmaxf(fmaxf(l.x, l.y), fmaxf(l.z, l.w));
    m4 = fmaxf(m4, __shfl_xor_sync(0xffffffffu, m4, 1));
    m4 = fmaxf(m4, __shfl_xor_sync(0xffffffffu, m4, 2));
    float se = __expf(l.x - m4) + __expf(l.y - m4) + __expf(l.z - m4) + __expf(l.w - m4);
    se += __shfl_xor_sync(0xffffffffu, se, 1);
    se += __shfl_xor_sync(0xffffffffu, se, 2);
    float lse = m4 + __logf(se);

    if (lane < 4) {
        float4 o;
        o.x = l.x - lse;
        o.y = l.y - lse;
        o.z = l.z - lse;
        o.w = l.w - lse;
        reinterpret_cast<float4*>(out)[(size_t)warp * 4 + q] = o;
    }
}

// ---------------- launch ----------------
extern "C" void kernel_launch(void* const* d_in, const int* in_sizes, int n_in,
                              void* d_out, int out_size) {
    const float* x  = (const float*)d_in[0];
    const int*   ei = (const int*)d_in[1];   // int32 (JAX x64 disabled)
    const float* W1 = (const float*)d_in[2];
    const float* b1 = (const float*)d_in[3];
    const float* W2 = (const float*)d_in[4];
    const float* b2 = (const float*)d_in[5];
    float*       out = (float*)d_out;

    int N = in_sizes[0] / F_IN;
    int E = in_sizes[1] / 2;
    const int TB = 256;

    hist_kernel<<<(E + TB - 1) / TB, TB>>>(ei, E);
    alloc_kernel<<<(N + SCAN_B - 1) / SCAN_B, SCAN_B>>>(N);
    fill_kernel<<<(E + TB - 1) / TB, TB>>>(ei, E);

    gemm1_kernel<<<(N + 127) / 128, TB>>>(x, W1, N);

    long long a1_threads = (long long)N * 32;
    agg1_kernel<<<(unsigned)((a1_threads + TB - 1) / TB), TB>>>(b1, W2, N);

    long long a2_threads = (long long)N * 32;
    agg2_kernel<<<(unsigned)((a2_threads + TB - 1) / TB), TB>>>(b2, out, N);
}

// round 8
// speedup vs baseline: 1.4352x; 1.1545x over previous
#include <cuda_runtime.h>
#include <cuda_fp16.h>
#include <math.h>

// ---------------- problem-size constants ----------------
#define MAXN 100000
#define MAXE 1200000
#define F_IN  64
#define F_HID 64
#define F_OUT 16
#define SCAN_B 256

// ---------------- device scratch (zero at load; re-zeroed at end of agg2) ----
__device__ __half g_y_h[MAXN * F_HID];   // x @ W1, fp16
__device__ __half g_h_h[MAXN * F_HID];   // relu layer-1 output, fp16
__device__ __half g_z_h[MAXN * F_OUT];   // h @ W2, fp16
__device__ int    g_deg[MAXN];           // out-degree by row (for dinv)
__device__ int    g_cnt[MAXN];           // in-degree by col (CSR counts)
__device__ float  g_dinv[MAXN];
__device__ int    g_start[MAXN];         // CSR row_ptr
__device__ int    g_cursor[MAXN];        // fill cursors
__device__ int    g_total;               // global CSR allocation cursor
__device__ int2   g_edge[MAXE];          // packed (src, coef bits), bucketed by col

// ---------------- kernels ----------------

// Histogram both endpoints. Assumes g_deg/g_cnt are zero on entry
// (true at module load; agg2 re-zeroes them every invocation).
__global__ void hist_kernel(const int* __restrict__ ei, int E) {
    int e = blockIdx.x * blockDim.x + threadIdx.x;
    if (e < E) {
        atomicAdd(&g_deg[ei[e]], 1);
        atomicAdd(&g_cnt[ei[E + e]], 1);
    }
}

// CSR allocation in ONE kernel: block-local inclusive scan of cnt + a single
// global atomicAdd per block for the base. Also computes dinv.
__global__ __launch_bounds__(SCAN_B) void alloc_kernel(int N) {
    __shared__ int s[SCAN_B];
    __shared__ int base_sm;
    int t = threadIdx.x;
    int i = blockIdx.x * SCAN_B + t;
    int v = (i < N) ? g_cnt[i] : 0;
    s[t] = v;
    if (i < N) g_dinv[i] = rsqrtf((float)(g_deg[i] + 1));
    __syncthreads();
    for (int off = 1; off < SCAN_B; off <<= 1) {
        int u = (t >= off) ? s[t - off] : 0;
        __syncthreads();
        s[t] += u;
        __syncthreads();
    }
    if (t == SCAN_B - 1) base_sm = atomicAdd(&g_total, s[t]);
    __syncthreads();
    if (i < N) {
        int st = base_sm + s[t] - v;
        g_start[i] = st;
        g_cursor[i] = st;
    }
}

// Fill CSR: packed (src, coef) records bucketed by col.
__global__ void fill_kernel(const int* __restrict__ ei, int E) {
    int e = blockIdx.x * blockDim.x + threadIdx.x;
    if (e < E) {
        int r = ei[e];
        int c = ei[E + e];
        float coef = g_dinv[r] * g_dinv[c];
        int pos = atomicAdd(&g_cursor[c], 1);
        g_edge[pos] = make_int2(r, __float_as_int(coef));
    }
}

// y = x @ W1 ([N,64] @ [64,64]) via HMMA m16n8k16, fp16 in / f32 accum / fp16 out.
// 256 threads = 8 warps; block covers 128 rows; each warp 16 rows x 64 cols.
__global__ __launch_bounds__(256) void gemm1_kernel(const float* __restrict__ x,
                                                    const float* __restrict__ W,
                                                    int N) {
    __shared__ __half xs[128 * 72];    // x tile fp16, row stride 72 (bank-safe)
    __shared__ __half W1t[64 * 72];    // W1 transposed: W1t[n][k]
    int tid  = threadIdx.x;
    int lane = tid & 31;
    int warp = tid >> 5;

    // W1 f32 row-major [k][n] -> fp16 transposed [n][k]
    for (int i = tid; i < 4096; i += 256) {
        int k = i >> 6, n = i & 63;
        W1t[n * 72 + k] = __float2half(W[i]);
    }

    int row0 = blockIdx.x * 128;
    // x tile: 128 rows x 16 float4, convert to fp16
    for (int i = tid; i < 2048; i += 256) {
        int r = i >> 4, c4 = i & 15;
        int gr = row0 + r;
        float4 v = (gr < N) ? reinterpret_cast<const float4*>(x)[(size_t)gr * 16 + c4]
                            : make_float4(0.f, 0.f, 0.f, 0.f);
        __half2 p0 = __floats2half2_rn(v.x, v.y);
        __half2 p1 = __floats2half2_rn(v.z, v.w);
        *reinterpret_cast<__half2*>(&xs[r * 72 + c4 * 4])     = p0;
        *reinterpret_cast<__half2*>(&xs[r * 72 + c4 * 4 + 2]) = p1;
    }
    __syncthreads();

    int rbase = warp * 16;
    int r  = lane >> 2;        // 0..7 (fragment row group)
    int kq = (lane & 3) * 2;   // fragment k offset

    float acc[8][4];
#pragma unroll
    for (int nt = 0; nt < 8; nt++)
#pragma unroll
        for (int j = 0; j < 4; j++) acc[nt][j] = 0.f;

#pragma unroll
    for (int kc = 0; kc < 4; kc++) {
        int k0 = kc * 16;
        unsigned a0 = *reinterpret_cast<unsigned*>(&xs[(rbase + r)     * 72 + k0 + kq]);
        unsigned a1 = *reinterpret_cast<unsigned*>(&xs[(rbase + r + 8) * 72 + k0 + kq]);
        unsigned a2 = *reinterpret_cast<unsigned*>(&xs[(rbase + r)     * 72 + k0 + kq + 8]);
        unsigned a3 = *reinterpret_cast<unsigned*>(&xs[(rbase + r + 8) * 72 + k0 + kq + 8]);
#pragma unroll
        for (int nt = 0; nt < 8; nt++) {
            int n = nt * 8 + r;
            unsigned b0 = *reinterpret_cast<unsigned*>(&W1t[n * 72 + k0 + kq]);
            unsigned b1 = *reinterpret_cast<unsigned*>(&W1t[n * 72 + k0 + kq + 8]);
            asm volatile(
                "mma.sync.aligned.m16n8k16.row.col.f32.f16.f16.f32 "
                "{%0,%1,%2,%3}, {%4,%5,%6,%7}, {%8,%9}, {%0,%1,%2,%3};"
                : "+f"(acc[nt][0]), "+f"(acc[nt][1]), "+f"(acc[nt][2]), "+f"(acc[nt][3])
                : "r"(a0), "r"(a1), "r"(a2), "r"(a3), "r"(b0), "r"(b1));
        }
    }

    int gr0 = row0 + rbase + r;
    int gr1 = gr0 + 8;
#pragma unroll
    for (int nt = 0; nt < 8; nt++) {
        int col = nt * 8 + (lane & 3) * 2;
        __half2 p0 = __floats2half2_rn(acc[nt][0], acc[nt][1]);
        __half2 p1 = __floats2half2_rn(acc[nt][2], acc[nt][3]);
        if (gr0 < N) *reinterpret_cast<__half2*>(&g_y_h[(size_t)gr0 * 64 + col]) = p0;
        if (gr1 < N) *reinterpret_cast<__half2*>(&g_y_h[(size_t)gr1 * 64 + col]) = p1;
    }
}

// Layer-1 aggregation: pure CSR gather + self loop + bias + relu -> h fp16.
// One warp per node; 4 neighbor rows in flight.
__global__ __launch_bounds__(256) void agg1_kernel(const float* __restrict__ b1, int N) {
    int tid = threadIdx.x;
    int warp = (blockIdx.x * blockDim.x + tid) >> 5;
    if (warp >= N) return;
    int lane = tid & 31;
    int slot = lane >> 3;     // 0..3 neighbor slot
    int q = lane & 7;         // uint4 (8-half) chunk within 128B row

    int start = g_start[warp];
    int cnt = g_cnt[warp];

    float a[8];
#pragma unroll
    for (int i = 0; i < 8; i++) a[i] = 0.f;

    const uint4* yrows = reinterpret_cast<const uint4*>(g_y_h);
    for (int j = slot; j < cnt; j += 4) {
        int2 rec = g_edge[start + j];
        float coef = __int_as_float(rec.y);
        uint4 v = yrows[(size_t)rec.x * 8 + q];
        float2 f;
        f = __half22float2(*reinterpret_cast<__half2*>(&v.x)); a[0] += coef * f.x; a[1] += coef * f.y;
        f = __half22float2(*reinterpret_cast<__half2*>(&v.y)); a[2] += coef * f.x; a[3] += coef * f.y;
        f = __half22float2(*reinterpret_cast<__half2*>(&v.z)); a[4] += coef * f.x; a[5] += coef * f.y;
        f = __half22float2(*reinterpret_cast<__half2*>(&v.w)); a[6] += coef * f.x; a[7] += coef * f.y;
    }
#pragma unroll
    for (int i = 0; i < 8; i++) {
        a[i] += __shfl_xor_sync(0xffffffffu, a[i], 8);
        a[i] += __shfl_xor_sync(0xffffffffu, a[i], 16);
    }

    if (lane < 8) {
        float di = g_dinv[warp];
        float s = di * di;
        uint4 yv = yrows[(size_t)warp * 8 + q];
        float2 y0 = __half22float2(*reinterpret_cast<__half2*>(&yv.x));
        float2 y1 = __half22float2(*reinterpret_cast<__half2*>(&yv.y));
        float2 y2 = __half22float2(*reinterpret_cast<__half2*>(&yv.z));
        float2 y3 = __half22float2(*reinterpret_cast<__half2*>(&yv.w));
        float4 bb0 = reinterpret_cast<const float4*>(b1)[q * 2];
        float4 bb1 = reinterpret_cast<const float4*>(b1)[q * 2 + 1];
        __half2 p0 = __floats2half2_rn(fmaxf(a[0] + s * y0.x + bb0.x, 0.f),
                                       fmaxf(a[1] + s * y0.y + bb0.y, 0.f));
        __half2 p1 = __floats2half2_rn(fmaxf(a[2] + s * y1.x + bb0.z, 0.f),
                                       fmaxf(a[3] + s * y1.y + bb0.w, 0.f));
        __half2 p2 = __floats2half2_rn(fmaxf(a[4] + s * y2.x + bb1.x, 0.f),
                                       fmaxf(a[5] + s * y2.y + bb1.y, 0.f));
        __half2 p3 = __floats2half2_rn(fmaxf(a[6] + s * y3.x + bb1.z, 0.f),
                                       fmaxf(a[7] + s * y3.y + bb1.w, 0.f));
        uint4 o;
        o.x = *reinterpret_cast<unsigned*>(&p0);
        o.y = *reinterpret_cast<unsigned*>(&p1);
        o.z = *reinterpret_cast<unsigned*>(&p2);
        o.w = *reinterpret_cast<unsigned*>(&p3);
        reinterpret_cast<uint4*>(g_h_h)[(size_t)warp * 8 + q] = o;
    }
}

// z = h @ W2 ([N,64] fp16 @ [64,16]) via HMMA m16n8k16 -> fp16.
// 256 threads = 8 warps; 128 rows per block; 2 n-tiles.
__global__ __launch_bounds__(256) void gemm2_kernel(const float* __restrict__ W2, int N) {
    __shared__ __half hs[128 * 72];
    __shared__ __half W2t[16 * 72];    // transposed: W2t[n][k]
    int tid  = threadIdx.x;
    int lane = tid & 31;
    int warp = tid >> 5;

    // W2 f32 [k][n] row-major -> fp16 transposed [n][k]
    for (int i = tid; i < 1024; i += 256) {
        int k = i >> 4, n = i & 15;
        W2t[n * 72 + k] = __float2half(W2[i]);
    }

    int row0 = blockIdx.x * 128;
    for (int i = tid; i < 1024; i += 256) {
        int r = i >> 3, c = i & 7;
        int gr = row0 + r;
        uint4 v = (gr < N) ? reinterpret_cast<const uint4*>(g_h_h)[(size_t)gr * 8 + c]
                           : make_uint4(0u, 0u, 0u, 0u);
        *reinterpret_cast<uint4*>(&hs[r * 72 + c * 8]) = v;
    }
    __syncthreads();

    int rbase = warp * 16;
    int r  = lane >> 2;
    int kq = (lane & 3) * 2;

    float acc[2][4];
#pragma unroll
    for (int nt = 0; nt < 2; nt++)
#pragma unroll
        for (int j = 0; j < 4; j++) acc[nt][j] = 0.f;

#pragma unroll
    for (int kc = 0; kc < 4; kc++) {
        int k0 = kc * 16;
        unsigned a0 = *reinterpret_cast<unsigned*>(&hs[(rbase + r)     * 72 + k0 + kq]);
        unsigned a1 = *reinterpret_cast<unsigned*>(&hs[(rbase + r + 8) * 72 + k0 + kq]);
        unsigned a2 = *reinterpret_cast<unsigned*>(&hs[(rbase + r)     * 72 + k0 + kq + 8]);
        unsigned a3 = *reinterpret_cast<unsigned*>(&hs[(rbase + r + 8) * 72 + k0 + kq + 8]);
#pragma unroll
        for (int nt = 0; nt < 2; nt++) {
            int n = nt * 8 + r;
            unsigned b0 = *reinterpret_cast<unsigned*>(&W2t[n * 72 + k0 + kq]);
            unsigned b1 = *reinterpret_cast<unsigned*>(&W2t[n * 72 + k0 + kq + 8]);
            asm volatile(
                "mma.sync.aligned.m16n8k16.row.col.f32.f16.f16.f32 "
                "{%0,%1,%2,%3}, {%4,%5,%6,%7}, {%8,%9}, {%0,%1,%2,%3};"
                : "+f"(acc[nt][0]), "+f"(acc[nt][1]), "+f"(acc[nt][2]), "+f"(acc[nt][3])
                : "r"(a0), "r"(a1), "r"(a2), "r"(a3), "r"(b0), "r"(b1));
        }
    }

    int gr0 = row0 + rbase + r;
    int gr1 = gr0 + 8;
#pragma unroll
    for (int nt = 0; nt < 2; nt++) {
        int col = nt * 8 + (lane & 3) * 2;
        __half2 p0 = __floats2half2_rn(acc[nt][0], acc[nt][1]);
        __half2 p1 = __floats2half2_rn(acc[nt][2], acc[nt][3]);
        if (gr0 < N) *reinterpret_cast<__half2*>(&g_z_h[(size_t)gr0 * 16 + col]) = p0;
        if (gr1 < N) *reinterpret_cast<__half2*>(&g_z_h[(size_t)gr1 * 16 + col]) = p1;
    }
}

// Fused: aggr2 (CSR gather of fp16 rows) + self loop + bias + log_softmax -> out.
// Also re-zeroes g_deg/g_cnt/g_total for the next graph replay.
__global__ __launch_bounds__(256) void agg2_kernel(const float* __restrict__ b2,
                                                   float* __restrict__ out, int N) {
    int tid = threadIdx.x;
    int warp = (blockIdx.x * blockDim.x + tid) >> 5;
    if (warp >= N) return;
    int lane = tid & 31;

    int start = g_start[warp];
    int cnt = g_cnt[warp];
    __syncwarp();
    if (lane == 0) { g_deg[warp] = 0; g_cnt[warp] = 0; }
    if (warp == 0 && lane == 1) g_total = 0;

    int slot = lane >> 2;    // 0..7 neighbor slot
    int q = lane & 3;        // uint2 (4-half) chunk within 32B row

    float a[4];
#pragma unroll
    for (int i = 0; i < 4; i++) a[i] = 0.f;

    const uint2* zrows = reinterpret_cast<const uint2*>(g_z_h);
    for (int j = slot; j < cnt; j += 8) {
        int2 rec = g_edge[start + j];
        float coef = __int_as_float(rec.y);
        uint2 v = zrows[(size_t)rec.x * 4 + q];
        float2 f0 = __half22float2(*reinterpret_cast<__half2*>(&v.x));
        float2 f1 = __half22float2(*reinterpret_cast<__half2*>(&v.y));
        a[0] += coef * f0.x;  a[1] += coef * f0.y;
        a[2] += coef * f1.x;  a[3] += coef * f1.y;
    }
#pragma unroll
    for (int i = 0; i < 4; i++) {
        a[i] += __shfl_xor_sync(0xffffffffu, a[i], 4);
        a[i] += __shfl_xor_sync(0xffffffffu, a[i], 8);
        a[i] += __shfl_xor_sync(0xffffffffu, a[i], 16);
    }

    float di = g_dinv[warp];
    float s = di * di;
    uint2 zv = zrows[(size_t)warp * 4 + q];
    float2 z0 = __half22float2(*reinterpret_cast<__half2*>(&zv.x));
    float2 z1 = __half22float2(*reinterpret_cast<__half2*>(&zv.y));
    float4 bb = reinterpret_cast<const float4*>(b2)[q];
    float4 l;
    l.x = a[0] + s * z0.x + bb.x;
    l.y = a[1] + s * z0.y + bb.y;
    l.z = a[2] + s * z1.x + bb.z;
    l.w = a[3] + s * z1.y + bb.w;

    float m4 = fmaxf(fmaxf(l.x, l.y), fmaxf(l.z, l.w));
    m4 = fmaxf(m4, __shfl_xor_sync(0xffffffffu, m4, 1));
    m4 = fmaxf(m4, __shfl_xor_sync(0xffffffffu, m4, 2));
    float se = __expf(l.x - m4) + __expf(l.y - m4) + __expf(l.z - m4) + __expf(l.w - m4);
    se += __shfl_xor_sync(0xffffffffu, se, 1);
    se += __shfl_xor_sync(0xffffffffu, se, 2);
    float lse = m4 + __logf(se);

    if (lane < 4) {
        float4 o;
        o.x = l.x - lse;
        o.y = l.y - lse;
        o.z = l.z - lse;
        o.w = l.w - lse;
        reinterpret_cast<float4*>(out)[(size_t)warp * 4 + q] = o;
    }
}

// ---------------- launch ----------------
extern "C" void kernel_launch(void* const* d_in, const int* in_sizes, int n_in,
                              void* d_out, int out_size) {
    const float* x  = (const float*)d_in[0];
    const int*   ei = (const int*)d_in[1];   // int32 (JAX x64 disabled)
    const float* W1 = (const float*)d_in[2];
    const float* b1 = (const float*)d_in[3];
    const float* W2 = (const float*)d_in[4];
    const float* b2 = (const float*)d_in[5];
    float*       out = (float*)d_out;

    int N = in_sizes[0] / F_IN;
    int E = in_sizes[1] / 2;
    const int TB = 256;

    hist_kernel<<<(E + TB - 1) / TB, TB>>>(ei, E);
    alloc_kernel<<<(N + SCAN_B - 1) / SCAN_B, SCAN_B>>>(N);
    fill_kernel<<<(E + TB - 1) / TB, TB>>>(ei, E);

    gemm1_kernel<<<(N + 127) / 128, TB>>>(x, W1, N);

    long long a1_threads = (long long)N * 32;
    agg1_kernel<<<(unsigned)((a1_threads + TB - 1) / TB), TB>>>(b1, N);

    gemm2_kernel<<<(N + 127) / 128, TB>>>(W2, N);

    long long a2_threads = (long long)N * 32;
    agg2_kernel<<<(unsigned)((a2_threads + TB - 1) / TB), TB>>>(b2, out, N);
}

// round 9
// speedup vs baseline: 1.4683x; 1.0231x over previous
#include <cuda_runtime.h>
#include <cuda_fp16.h>
#include <math.h>

// ---------------- problem-size constants ----------------
#define MAXN 100000
#define MAXE 1200000
#define F_IN  64
#define F_HID 64
#define F_OUT 16
#define SCAN_B 256

// ---------------- device scratch (zero at load; re-zeroed at end of agg2) ----
__device__ __half g_y_h[MAXN * F_HID];   // x @ W1, fp16
__device__ __half g_h_h[MAXN * F_HID];   // relu layer-1 output, fp16
__device__ __half g_z_h[MAXN * F_OUT];   // h @ W2, fp16
__device__ int    g_deg[MAXN];           // out-degree by row (for dinv)
__device__ int    g_cnt[MAXN];           // in-degree by col (CSR counts)
__device__ float  g_dinv[MAXN];
__device__ int    g_start[MAXN];         // CSR row_ptr
__device__ int    g_cursor[MAXN];        // fill cursors
__device__ int    g_total;               // global CSR allocation cursor
__device__ int2   g_edge[MAXE];          // packed (src, coef bits), bucketed by col

// ---------------- kernels ----------------

// Histogram both endpoints. Assumes g_deg/g_cnt are zero on entry
// (true at module load; agg2 re-zeroes them every invocation).
__global__ void hist_kernel(const int* __restrict__ ei, int E) {
    int e = blockIdx.x * blockDim.x + threadIdx.x;
    if (e < E) {
        atomicAdd(&g_deg[ei[e]], 1);
        atomicAdd(&g_cnt[ei[E + e]], 1);
    }
}

// CSR allocation in ONE kernel: block-local inclusive scan of cnt + a single
// global atomicAdd per block for the base. Also computes dinv.
__global__ __launch_bounds__(SCAN_B) void alloc_kernel(int N) {
    __shared__ int s[SCAN_B];
    __shared__ int base_sm;
    int t = threadIdx.x;
    int i = blockIdx.x * SCAN_B + t;
    int v = (i < N) ? g_cnt[i] : 0;
    s[t] = v;
    if (i < N) g_dinv[i] = rsqrtf((float)(g_deg[i] + 1));
    __syncthreads();
    for (int off = 1; off < SCAN_B; off <<= 1) {
        int u = (t >= off) ? s[t - off] : 0;
        __syncthreads();
        s[t] += u;
        __syncthreads();
    }
    if (t == SCAN_B - 1) base_sm = atomicAdd(&g_total, s[t]);
    __syncthreads();
    if (i < N) {
        int st = base_sm + s[t] - v;
        g_start[i] = st;
        g_cursor[i] = st;
    }
}

// Fill CSR: packed (src, coef) records bucketed by col.
__global__ void fill_kernel(const int* __restrict__ ei, int E) {
    int e = blockIdx.x * blockDim.x + threadIdx.x;
    if (e < E) {
        int r = ei[e];
        int c = ei[E + e];
        float coef = g_dinv[r] * g_dinv[c];
        int pos = atomicAdd(&g_cursor[c], 1);
        g_edge[pos] = make_int2(r, __float_as_int(coef));
    }
}

// y = x @ W1 ([N,64] @ [64,64]) via HMMA m16n8k16.
// A-fragments loaded DIRECTLY from global (fp32 -> fp16 in regs): no x smem
// stage, no block-wide load barrier; each warp runs independently (MLP=16).
__global__ __launch_bounds__(256) void gemm1_kernel(const float* __restrict__ x,
                                                    const float* __restrict__ W,
                                                    int N) {
    __shared__ __half W1t[64 * 72];    // W1 transposed: W1t[n][k]
    int tid  = threadIdx.x;
    int lane = tid & 31;
    int warp = tid >> 5;

    // W1 f32 row-major [k][n] -> fp16 transposed [n][k]
    for (int i = tid; i < 4096; i += 256) {
        int k = i >> 6, n = i & 63;
        W1t[n * 72 + k] = __float2half(W[i]);
    }
    __syncthreads();

    int row0 = blockIdx.x * 128 + warp * 16;
    int r  = lane >> 2;        // 0..7 fragment row
    int kq = (lane & 3) * 2;   // fragment k offset
    int gr0 = row0 + r;
    int gr1 = row0 + r + 8;
    int sr0 = min(gr0, N - 1);
    int sr1 = min(gr1, N - 1);

    // Load all A fragments up front: 16 independent LDG.64
    unsigned a[4][4];
#pragma unroll
    for (int kc = 0; kc < 4; kc++) {
        int k0 = kc * 16;
        float2 f0 = *reinterpret_cast<const float2*>(&x[(size_t)sr0 * 64 + k0 + kq]);
        float2 f1 = *reinterpret_cast<const float2*>(&x[(size_t)sr1 * 64 + k0 + kq]);
        float2 f2 = *reinterpret_cast<const float2*>(&x[(size_t)sr0 * 64 + k0 + kq + 8]);
        float2 f3 = *reinterpret_cast<const float2*>(&x[(size_t)sr1 * 64 + k0 + kq + 8]);
        __half2 h0 = __floats2half2_rn(f0.x, f0.y);
        __half2 h1 = __floats2half2_rn(f1.x, f1.y);
        __half2 h2 = __floats2half2_rn(f2.x, f2.y);
        __half2 h3 = __floats2half2_rn(f3.x, f3.y);
        a[kc][0] = *reinterpret_cast<unsigned*>(&h0);
        a[kc][1] = *reinterpret_cast<unsigned*>(&h1);
        a[kc][2] = *reinterpret_cast<unsigned*>(&h2);
        a[kc][3] = *reinterpret_cast<unsigned*>(&h3);
    }

    float acc[8][4];
#pragma unroll
    for (int nt = 0; nt < 8; nt++)
#pragma unroll
        for (int j = 0; j < 4; j++) acc[nt][j] = 0.f;

#pragma unroll
    for (int kc = 0; kc < 4; kc++) {
        int k0 = kc * 16;
#pragma unroll
        for (int nt = 0; nt < 8; nt++) {
            int n = nt * 8 + r;
            unsigned b0 = *reinterpret_cast<unsigned*>(&W1t[n * 72 + k0 + kq]);
            unsigned b1 = *reinterpret_cast<unsigned*>(&W1t[n * 72 + k0 + kq + 8]);
            asm volatile(
                "mma.sync.aligned.m16n8k16.row.col.f32.f16.f16.f32 "
                "{%0,%1,%2,%3}, {%4,%5,%6,%7}, {%8,%9}, {%0,%1,%2,%3};"
                : "+f"(acc[nt][0]), "+f"(acc[nt][1]), "+f"(acc[nt][2]), "+f"(acc[nt][3])
                : "r"(a[kc][0]), "r"(a[kc][1]), "r"(a[kc][2]), "r"(a[kc][3]),
                  "r"(b0), "r"(b1));
        }
    }

#pragma unroll
    for (int nt = 0; nt < 8; nt++) {
        int col = nt * 8 + (lane & 3) * 2;
        __half2 p0 = __floats2half2_rn(acc[nt][0], acc[nt][1]);
        __half2 p1 = __floats2half2_rn(acc[nt][2], acc[nt][3]);
        if (gr0 < N) *reinterpret_cast<__half2*>(&g_y_h[(size_t)gr0 * 64 + col]) = p0;
        if (gr1 < N) *reinterpret_cast<__half2*>(&g_y_h[(size_t)gr1 * 64 + col]) = p1;
    }
}

// Layer-1 aggregation: pure CSR gather + self loop + bias + relu -> h fp16.
// One warp per node; unrolled x2: 8 neighbor rows in flight.
__global__ __launch_bounds__(256) void agg1_kernel(const float* __restrict__ b1, int N) {
    int tid = threadIdx.x;
    int warp = (blockIdx.x * blockDim.x + tid) >> 5;
    if (warp >= N) return;
    int lane = tid & 31;
    int slot = lane >> 3;     // 0..3 neighbor slot
    int q = lane & 7;         // uint4 (8-half) chunk within 128B row

    int start = g_start[warp];
    int cnt = g_cnt[warp];

    float a[8];
#pragma unroll
    for (int i = 0; i < 8; i++) a[i] = 0.f;

    const uint4* yrows = reinterpret_cast<const uint4*>(g_y_h);
    int j = slot;
    for (; j + 4 < cnt; j += 8) {
        int2 r0 = g_edge[start + j];
        int2 r1 = g_edge[start + j + 4];
        float c0 = __int_as_float(r0.y);
        float c1 = __int_as_float(r1.y);
        uint4 v0 = yrows[(size_t)r0.x * 8 + q];
        uint4 v1 = yrows[(size_t)r1.x * 8 + q];
        float2 f;
        f = __half22float2(*reinterpret_cast<__half2*>(&v0.x)); a[0] += c0 * f.x; a[1] += c0 * f.y;
        f = __half22float2(*reinterpret_cast<__half2*>(&v0.y)); a[2] += c0 * f.x; a[3] += c0 * f.y;
        f = __half22float2(*reinterpret_cast<__half2*>(&v0.z)); a[4] += c0 * f.x; a[5] += c0 * f.y;
        f = __half22float2(*reinterpret_cast<__half2*>(&v0.w)); a[6] += c0 * f.x; a[7] += c0 * f.y;
        f = __half22float2(*reinterpret_cast<__half2*>(&v1.x)); a[0] += c1 * f.x; a[1] += c1 * f.y;
        f = __half22float2(*reinterpret_cast<__half2*>(&v1.y)); a[2] += c1 * f.x; a[3] += c1 * f.y;
        f = __half22float2(*reinterpret_cast<__half2*>(&v1.z)); a[4] += c1 * f.x; a[5] += c1 * f.y;
        f = __half22float2(*reinterpret_cast<__half2*>(&v1.w)); a[6] += c1 * f.x; a[7] += c1 * f.y;
    }
    if (j < cnt) {
        int2 r0 = g_edge[start + j];
        float c0 = __int_as_float(r0.y);
        uint4 v0 = yrows[(size_t)r0.x * 8 + q];
        float2 f;
        f = __half22float2(*reinterpret_cast<__half2*>(&v0.x)); a[0] += c0 * f.x; a[1] += c0 * f.y;
        f = __half22float2(*reinterpret_cast<__half2*>(&v0.y)); a[2] += c0 * f.x; a[3] += c0 * f.y;
        f = __half22float2(*reinterpret_cast<__half2*>(&v0.z)); a[4] += c0 * f.x; a[5] += c0 * f.y;
        f = __half22float2(*reinterpret_cast<__half2*>(&v0.w)); a[6] += c0 * f.x; a[7] += c0 * f.y;
    }
#pragma unroll
    for (int i = 0; i < 8; i++) {
        a[i] += __shfl_xor_sync(0xffffffffu, a[i], 8);
        a[i] += __shfl_xor_sync(0xffffffffu, a[i], 16);
    }

    if (lane < 8) {
        float di = g_dinv[warp];
        float s = di * di;
        uint4 yv = yrows[(size_t)warp * 8 + q];
        float2 y0 = __half22float2(*reinterpret_cast<__half2*>(&yv.x));
        float2 y1 = __half22float2(*reinterpret_cast<__half2*>(&yv.y));
        float2 y2 = __half22float2(*reinterpret_cast<__half2*>(&yv.z));
        float2 y3 = __half22float2(*reinterpret_cast<__half2*>(&yv.w));
        float4 bb0 = reinterpret_cast<const float4*>(b1)[q * 2];
        float4 bb1 = reinterpret_cast<const float4*>(b1)[q * 2 + 1];
        __half2 p0 = __floats2half2_rn(fmaxf(a[0] + s * y0.x + bb0.x, 0.f),
                                       fmaxf(a[1] + s * y0.y + bb0.y, 0.f));
        __half2 p1 = __floats2half2_rn(fmaxf(a[2] + s * y1.x + bb0.z, 0.f),
                                       fmaxf(a[3] + s * y1.y + bb0.w, 0.f));
        __half2 p2 = __floats2half2_rn(fmaxf(a[4] + s * y2.x + bb1.x, 0.f),
                                       fmaxf(a[5] + s * y2.y + bb1.y, 0.f));
        __half2 p3 = __floats2half2_rn(fmaxf(a[6] + s * y3.x + bb1.z, 0.f),
                                       fmaxf(a[7] + s * y3.y + bb1.w, 0.f));
        uint4 o;
        o.x = *reinterpret_cast<unsigned*>(&p0);
        o.y = *reinterpret_cast<unsigned*>(&p1);
        o.z = *reinterpret_cast<unsigned*>(&p2);
        o.w = *reinterpret_cast<unsigned*>(&p3);
        reinterpret_cast<uint4*>(g_h_h)[(size_t)warp * 8 + q] = o;
    }
}

// z = h @ W2 ([N,64] fp16 @ [64,16]) via HMMA m16n8k16 -> fp16.
// 256 threads = 8 warps; 128 rows per block; 2 n-tiles.
__global__ __launch_bounds__(256) void gemm2_kernel(const float* __restrict__ W2, int N) {
    __shared__ __half hs[128 * 72];
    __shared__ __half W2t[16 * 72];    // transposed: W2t[n][k]
    int tid  = threadIdx.x;
    int lane = tid & 31;
    int warp = tid >> 5;

    // W2 f32 [k][n] row-major -> fp16 transposed [n][k]
    for (int i = tid; i < 1024; i += 256) {
        int k = i >> 4, n = i & 15;
        W2t[n * 72 + k] = __float2half(W2[i]);
    }

    int row0 = blockIdx.x * 128;
    for (int i = tid; i < 1024; i += 256) {
        int r = i >> 3, c = i & 7;
        int gr = row0 + r;
        uint4 v = (gr < N) ? reinterpret_cast<const uint4*>(g_h_h)[(size_t)gr * 8 + c]
                           : make_uint4(0u, 0u, 0u, 0u);
        *reinterpret_cast<uint4*>(&hs[r * 72 + c * 8]) = v;
    }
    __syncthreads();

    int rbase = warp * 16;
    int r  = lane >> 2;
    int kq = (lane & 3) * 2;

    float acc[2][4];
#pragma unroll
    for (int nt = 0; nt < 2; nt++)
#pragma unroll
        for (int j = 0; j < 4; j++) acc[nt][j] = 0.f;

#pragma unroll
    for (int kc = 0; kc < 4; kc++) {
        int k0 = kc * 16;
        unsigned a0 = *reinterpret_cast<unsigned*>(&hs[(rbase + r)     * 72 + k0 + kq]);
        unsigned a1 = *reinterpret_cast<unsigned*>(&hs[(rbase + r + 8) * 72 + k0 + kq]);
        unsigned a2 = *reinterpret_cast<unsigned*>(&hs[(rbase + r)     * 72 + k0 + kq + 8]);
        unsigned a3 = *reinterpret_cast<unsigned*>(&hs[(rbase + r + 8) * 72 + k0 + kq + 8]);
#pragma unroll
        for (int nt = 0; nt < 2; nt++) {
            int n = nt * 8 + r;
            unsigned b0 = *reinterpret_cast<unsigned*>(&W2t[n * 72 + k0 + kq]);
            unsigned b1 = *reinterpret_cast<unsigned*>(&W2t[n * 72 + k0 + kq + 8]);
            asm volatile(
                "mma.sync.aligned.m16n8k16.row.col.f32.f16.f16.f32 "
                "{%0,%1,%2,%3}, {%4,%5,%6,%7}, {%8,%9}, {%0,%1,%2,%3};"
                : "+f"(acc[nt][0]), "+f"(acc[nt][1]), "+f"(acc[nt][2]), "+f"(acc[nt][3])
                : "r"(a0), "r"(a1), "r"(a2), "r"(a3), "r"(b0), "r"(b1));
        }
    }

    int gr0 = row0 + rbase + r;
    int gr1 = gr0 + 8;
#pragma unroll
    for (int nt = 0; nt < 2; nt++) {
        int col = nt * 8 + (lane & 3) * 2;
        __half2 p0 = __floats2half2_rn(acc[nt][0], acc[nt][1]);
        __half2 p1 = __floats2half2_rn(acc[nt][2], acc[nt][3]);
        if (gr0 < N) *reinterpret_cast<__half2*>(&g_z_h[(size_t)gr0 * 16 + col]) = p0;
        if (gr1 < N) *reinterpret_cast<__half2*>(&g_z_h[(size_t)gr1 * 16 + col]) = p1;
    }
}

// Fused: aggr2 (CSR gather of fp16 rows) + self loop + bias + log_softmax -> out.
// Also re-zeroes g_deg/g_cnt/g_total for the next graph replay.
__global__ __launch_bounds__(256) void agg2_kernel(const float* __restrict__ b2,
                                                   float* __restrict__ out, int N) {
    int tid = threadIdx.x;
    int warp = (blockIdx.x * blockDim.x + tid) >> 5;
    if (warp >= N) return;
    int lane = tid & 31;

    int start = g_start[warp];
    int cnt = g_cnt[warp];
    __syncwarp();
    if (lane == 0) { g_deg[warp] = 0; g_cnt[warp] = 0; }
    if (warp == 0 && lane == 1) g_total = 0;

    int slot = lane >> 2;    // 0..7 neighbor slot
    int q = lane & 3;        // uint2 (4-half) chunk within 32B row

    float a[4];
#pragma unroll
    for (int i = 0; i < 4; i++) a[i] = 0.f;

    const uint2* zrows = reinterpret_cast<const uint2*>(g_z_h);
    for (int j = slot; j < cnt; j += 8) {
        int2 rec = g_edge[start + j];
        float coef = __int_as_float(rec.y);
        uint2 v = zrows[(size_t)rec.x * 4 + q];
        float2 f0 = __half22float2(*reinterpret_cast<__half2*>(&v.x));
        float2 f1 = __half22float2(*reinterpret_cast<__half2*>(&v.y));
        a[0] += coef * f0.x;  a[1] += coef * f0.y;
        a[2] += coef * f1.x;  a[3] += coef * f1.y;
    }
#pragma unroll
    for (int i = 0; i < 4; i++) {
        a[i] += __shfl_xor_sync(0xffffffffu, a[i], 4);
        a[i] += __shfl_xor_sync(0xffffffffu, a[i], 8);
        a[i] += __shfl_xor_sync(0xffffffffu, a[i], 16);
    }

    float di = g_dinv[warp];
    float s = di * di;
    uint2 zv = zrows[(size_t)warp * 4 + q];
    float2 z0 = __half22float2(*reinterpret_cast<__half2*>(&zv.x));
    float2 z1 = __half22float2(*reinterpret_cast<__half2*>(&zv.y));
    float4 bb = reinterpret_cast<const float4*>(b2)[q];
    float4 l;
    l.x = a[0] + s * z0.x + bb.x;
    l.y = a[1] + s * z0.y + bb.y;
    l.z = a[2] + s * z1.x + bb.z;
    l.w = a[3] + s * z1.y + bb.w;

    float m4 = fmaxf(fmaxf(l.x, l.y), fmaxf(l.z, l.w));
    m4 = fmaxf(m4, __shfl_xor_sync(0xffffffffu, m4, 1));
    m4 = fmaxf(m4, __shfl_xor_sync(0xffffffffu, m4, 2));
    float se = __expf(l.x - m4) + __expf(l.y - m4) + __expf(l.z - m4) + __expf(l.w - m4);
    se += __shfl_xor_sync(0xffffffffu, se, 1);
    se += __shfl_xor_sync(0xffffffffu, se, 2);
    float lse = m4 + __logf(se);

    if (lane < 4) {
        float4 o;
        o.x = l.x - lse;
        o.y = l.y - lse;
        o.z = l.z - lse;
        o.w = l.w - lse;
        reinterpret_cast<float4*>(out)[(size_t)warp * 4 + q] = o;
    }
}

// ---------------- launch ----------------
extern "C" void kernel_launch(void* const* d_in, const int* in_sizes, int n_in,
                              void* d_out, int out_size) {
    const float* x  = (const float*)d_in[0];
    const int*   ei = (const int*)d_in[1];   // int32 (JAX x64 disabled)
    const float* W1 = (const float*)d_in[2];
    const float* b1 = (const float*)d_in[3];
    const float* W2 = (const float*)d_in[4];
    const float* b2 = (const float*)d_in[5];
    float*       out = (float*)d_out;

    int N = in_sizes[0] / F_IN;
    int E = in_sizes[1] / 2;
    const int TB = 256;

    hist_kernel<<<(E + TB - 1) / TB, TB>>>(ei, E);
    alloc_kernel<<<(N + SCAN_B - 1) / SCAN_B, SCAN_B>>>(N);
    fill_kernel<<<(E + TB - 1) / TB, TB>>>(ei, E);

    gemm1_kernel<<<(N + 127) / 128, TB>>>(x, W1, N);

    long long a1_threads = (long long)N * 32;
    agg1_kernel<<<(unsigned)((a1_threads + TB - 1) / TB), TB>>>(b1, N);

    gemm2_kernel<<<(N + 127) / 128, TB>>>(W2, N);

    long long a2_threads = (long long)N * 32;
    agg2_kernel<<<(unsigned)((a2_threads + TB - 1) / TB), TB>>>(b2, out, N);
}